// round 1
// baseline (speedup 1.0000x reference)
#include <cuda_runtime.h>
#include <cstdint>

// APoT (8-bit, m=2) quantizer, eval forward:
//   apos   = |alpha| + 1e-5
//   a      = clamp(x / apos, -1, 1)           (fp32 IEEE division, RN)
//   q(a)   = nearest codebook level, tie -> smaller value (lower index)
//   out    = q(a) * apos
//
// Codebook levels (positive side) are exactly:  2^-e * (1 + 2^-d),
// e in [1,15], d in [1, 15-e], plus the pure powers 2^-e and 0.
// Equivalently: level = B + off, B = 2^-e, off in {0} U {2^-k : 2^-15 <= 2^-k <= B}.
// All levels are multiples of 2^-15; min positive level = 2^-15.
//
// Nearest-level with exact tie semantics reduces to rounding the exact
// fraction f = m - B (Sterbenz-exact) to the nearest allowed power of two:
//   - interior (f >= 2^-15): pick between L = 2^floor(log2 f) and 2L,
//     threshold 1.5L  (<= for positive a, < for negative a)
//   - low (f < 2^-15): pick between 0 and 2^-15, threshold 2^-16
//   - whole-value low (m < 2^-15): pick between 0 and 2^-15, threshold 2^-16
// The reference's |a-left| <= |a-right| comparisons are exact real
// comparisons (same-binade subtractions are exact), so these threshold
// compares reproduce them bit-for-bit. The sign-dependent tie break
// (<= vs <) is done on bit patterns: uf <= thr - signbit.

__device__ __forceinline__ float apot_quant(float x, float apos) {
    // IEEE round-to-nearest division: bit-identical to reference x / alpha_pos
    float a = __fdiv_rn(x, apos);
    a = fminf(fmaxf(a, -1.0f), 1.0f);

    unsigned ua = __float_as_uint(a);
    unsigned s  = ua >> 31;                 // 1 if negative (tie-break adjust)
    unsigned um = ua & 0x7FFFFFFFu;         // |a| bits
    unsigned uB = um & 0xFF800000u;         // binade base B = 2^-e (bits)
    float    m  = __uint_as_float(um);
    float    B  = __uint_as_float(uB);
    float    f  = m - B;                    // exact (Sterbenz)
    unsigned uf = __float_as_uint(f);
    unsigned uL = uf & 0xFF800000u;         // L = 2^floor(log2 f) (bits), 0 if f==0

    const unsigned C15 = 0x38000000u;       // bits(2^-15)
    const unsigned C16 = 0x37800000u;       // bits(2^-16)

    // interior: f vs 1.5*L  (bits(1.5L) = uL | 0x00400000)
    unsigned offI = (uf <= ((uL | 0x00400000u) - s)) ? uL : (uL + 0x00800000u);
    // low fraction: f vs 2^-16 -> 0 or 2^-15
    unsigned thrL = C16 - s;
    unsigned offL = (uf <= thrL) ? 0u : C15;
    unsigned off  = (uL >= C15) ? offI : offL;

    float v = B + __uint_as_float(off);     // exact: both dyadic, ratio <= 2^14

    // whole value below smallest level's binade: candidates {0, 2^-15}
    if (uB < C15) {
        v = (um <= thrL) ? 0.0f : __uint_as_float(C15);
    }

    unsigned uv = __float_as_uint(v) | (s << 31);
    return __uint_as_float(uv) * apos;      // same fp32 product as reference
}

__global__ void __launch_bounds__(256)
apot_kernel(const float* __restrict__ x,
            const float* __restrict__ alpha,
            float* __restrict__ out,
            int n)
{
    float apos = fabsf(__ldg(alpha)) + 1e-5f;

    int n4      = n >> 2;
    int gtid    = blockIdx.x * blockDim.x + threadIdx.x;
    int gstride = gridDim.x * blockDim.x;

    const float4* __restrict__ x4 = reinterpret_cast<const float4*>(x);
    float4* __restrict__ o4       = reinterpret_cast<float4*>(out);

    for (int i = gtid; i < n4; i += gstride) {
        float4 v = x4[i];
        float4 o;
        o.x = apot_quant(v.x, apos);
        o.y = apot_quant(v.y, apos);
        o.z = apot_quant(v.z, apos);
        o.w = apot_quant(v.w, apos);
        o4[i] = o;
    }
    // scalar tail (n not divisible by 4)
    for (int i = (n4 << 2) + gtid; i < n; i += gstride) {
        out[i] = apot_quant(x[i], apos);
    }
}

extern "C" void kernel_launch(void* const* d_in, const int* in_sizes, int n_in,
                              void* d_out, int out_size)
{
    const float* x     = (const float*)d_in[0];   // x: fp32 [4096*8192]
    const float* alpha = (const float*)d_in[1];   // alpha: fp32 scalar
    // d_in[2] = codebook (fp32 [243]) — deterministic APoT set, reproduced
    // arithmetically in-kernel; not read.
    float* out = (float*)d_out;

    int n = in_sizes[0];
    int n4 = n >> 2;

    const int threads = 256;
    // ~2 vectorized iterations per thread
    int blocks = (n4 + threads * 2 - 1) / (threads * 2);
    if (blocks < 1) blocks = 1;

    apot_kernel<<<blocks, threads>>>(x, alpha, out, n);
}

// round 2
// speedup vs baseline: 1.1766x; 1.1766x over previous
#include <cuda_runtime.h>
#include <cstdint>

// APoT (8-bit, m=2) quantizer, eval forward:
//   apos = |alpha| + 1e-5
//   a    = clamp(RN(x / apos), -1, 1)
//   q(a) = nearest codebook level, tie -> smaller value
//   out  = q(a) * apos
//
// Codebook positive levels are exactly {B + off}: B = 2^-e (e in [0,15]),
// off in {0} U {2^-k : 2^-15 <= 2^-k <= B}; min positive level 2^-15.
// Nearest-with-tie reduces to rounding the exact fraction f = m - B
// (Sterbenz) to the nearest allowed power of two. Implemented branch-free:
//
//   fu = interior ? bits(f) : bits(m)      (interior: B >= 2^-15)
//   Bf = interior ? B : 0
//   t  = fu + 0x3FFFFF + s                 (s = signbit: tie direction)
//     -> mantissa field >= 0x400001-s (i.e. f beyond tie point) carries
//        into the exponent: (t & 0xFF800000) = rounded power of two
//   off = (t <= 0x37BFFFFF) ? 0 : max(t & 0xFF800000, 2^-15)
//        (t <= C16+0x3FFFFF  <=>  fu + s <= bits(2^-16): below-the-floor
//         half-interval -> snap to 0; umax enforces the 2^-15 offset floor)
//   v  = Bf + off   (exact), sign restored, out = v * apos.
//
// Division: Markstein sequence with r = __frcp_rn(apos) (correctly rounded
// reciprocal). q0 = RN(x*r); e = RN(x - apos*q0); a = RN(q0 + e*r) is the
// correctly rounded quotient -> bit-identical to __fdiv_rn / the reference.

__device__ __forceinline__ float apot_quant(float x, float apos, float r) {
    // correctly-rounded x / apos (Markstein)
    float q0 = x * r;
    float e  = fmaf(-apos, q0, x);
    float a  = fmaf(e, r, q0);

    unsigned ua = __float_as_uint(a);
    unsigned s  = ua >> 31;                                   // tie direction
    unsigned um = umin(ua & 0x7FFFFFFFu, 0x3F800000u);        // |a| clamped to 1
    unsigned uB = um & 0x7F800000u;                           // binade base bits
    float    f  = __uint_as_float(um) - __uint_as_float(uB);  // exact
    unsigned uf = __float_as_uint(f);

    const unsigned C15 = 0x38000000u;                         // bits(2^-15)
    bool interior = (uB >= C15);
    unsigned fu = interior ? uf : um;                         // low: round m itself
    float    Bf = interior ? __uint_as_float(uB) : 0.0f;

    unsigned t   = fu + 0x3FFFFFu + s;                        // round-to-pow2 add trick
    unsigned rb  = umax(t & 0xFF800000u, C15);                // offset floor 2^-15
    unsigned off = (t <= 0x37BFFFFFu) ? 0u : rb;              // snap-to-zero half

    float v = Bf + __uint_as_float(off);                      // exact codebook level
    unsigned uv = __float_as_uint(v) | (ua & 0x80000000u);    // restore sign
    return __uint_as_float(uv) * apos;
}

__device__ __forceinline__ float4 quant4(float4 v, float apos, float r) {
    float4 o;
    o.x = apot_quant(v.x, apos, r);
    o.y = apot_quant(v.y, apos, r);
    o.z = apot_quant(v.z, apos, r);
    o.w = apot_quant(v.w, apos, r);
    return o;
}

__global__ void __launch_bounds__(256)
apot_kernel(const float* __restrict__ x,
            const float* __restrict__ alpha,
            float* __restrict__ out,
            int n)
{
    float apos = fabsf(__ldg(alpha)) + 1e-5f;
    float r    = __frcp_rn(apos);          // once per thread

    const float4* __restrict__ x4 = reinterpret_cast<const float4*>(x);
    float4* __restrict__ o4       = reinterpret_cast<float4*>(out);

    int n4 = n >> 2;
    // two float4 per thread, loads front-batched for MLP
    int i0 = blockIdx.x * (blockDim.x * 2) + threadIdx.x;
    int i1 = i0 + blockDim.x;

    bool p0 = i0 < n4;
    bool p1 = i1 < n4;
    float4 va, vb;
    if (p0) va = __ldcs(&x4[i0]);
    if (p1) vb = __ldcs(&x4[i1]);

    if (p0) __stcs(&o4[i0], quant4(va, apos, r));
    if (p1) __stcs(&o4[i1], quant4(vb, apos, r));

    // scalar tail (n not divisible by 4) — only low global threads hit this
    int gtid = blockIdx.x * blockDim.x + threadIdx.x;
    for (int i = (n4 << 2) + gtid; i < n; i += gridDim.x * blockDim.x) {
        out[i] = apot_quant(x[i], apos, r);
    }
}

extern "C" void kernel_launch(void* const* d_in, const int* in_sizes, int n_in,
                              void* d_out, int out_size)
{
    const float* x     = (const float*)d_in[0];   // x: fp32
    const float* alpha = (const float*)d_in[1];   // alpha: fp32 scalar
    // d_in[2] = codebook — deterministic APoT set, reproduced arithmetically.
    float* out = (float*)d_out;

    int n  = in_sizes[0];
    int n4 = n >> 2;

    const int threads = 256;
    int blocks = (n4 + threads * 2 - 1) / (threads * 2);
    if (blocks < 1) blocks = 1;

    apot_kernel<<<blocks, threads>>>(x, alpha, out, n);
}